// round 1
// baseline (speedup 1.0000x reference)
#include <cuda_runtime.h>
#include <math.h>

// Problem constants
#define BB     64
#define TT     2048
#define DD     40
#define HH     164
#define NOUT   7
#define JT     4              // hidden columns per CTA
#define NCOL   (HH / JT)      // 41 CTAs per layer
#define NLAYER 3
#define NCTA   (NCOL * NLAYER) // 123 CTAs total (< 148 SMs -> all co-resident)
#define TB     128            // threads per CTA

// ---------------- device scratch (no allocations allowed) ----------------
__device__ float    g_xT[TT * DD * BB];          // x transposed: [t][d][b]
__device__ float    g_h[NLAYER * 2 * HH * BB];   // h ring buffers: [l][parity][j][b]
__device__ unsigned g_cnt;                       // barrier arrival counter
__device__ unsigned g_rel;                       // barrier release phase

// ---------------- helpers ----------------
__device__ __forceinline__ unsigned long long fma2(unsigned long long a,
                                                   unsigned long long b,
                                                   unsigned long long c) {
    unsigned long long d;
    asm("fma.rn.f32x2 %0, %1, %2, %3;" : "=l"(d) : "l"(a), "l"(b), "l"(c));
    return d;
}
__device__ __forceinline__ unsigned long long splat2(float w) {
    unsigned long long v = (unsigned long long)__float_as_uint(w);
    return v | (v << 32);
}
__device__ __forceinline__ float lo2(unsigned long long v) { return __uint_as_float((unsigned)v); }
__device__ __forceinline__ float hi2(unsigned long long v) { return __uint_as_float((unsigned)(v >> 32)); }

// ---------------- init: zero ring buffers + barrier words ----------------
__global__ void k_init() {
    const int n = NLAYER * 2 * HH * BB;
    for (int i = blockIdx.x * blockDim.x + threadIdx.x; i < n; i += gridDim.x * blockDim.x)
        g_h[i] = 0.f;
    if (blockIdx.x == 0 && threadIdx.x == 0) { g_cnt = 0u; g_rel = 0u; }
}

// ---------------- transpose x[B][T][D] -> g_xT[t][d][b] ----------------
__global__ void k_transpose(const float* __restrict__ x) {
    __shared__ float s[BB * DD];
    const int t = blockIdx.x;
    for (int idx = threadIdx.x; idx < BB * DD; idx += blockDim.x) {
        int b = idx / DD, d = idx - b * DD;
        s[idx] = x[(b * TT + t) * DD + d];   // coalesced runs of 40
    }
    __syncthreads();
    for (int idx = threadIdx.x; idx < BB * DD; idx += blockDim.x) {
        int d = idx >> 6, b = idx & 63;      // BB == 64
        g_xT[t * DD * BB + idx] = s[b * DD + d];  // coalesced writes
    }
}

// ---------------- persistent wavefront LSTM ----------------
__global__ void __launch_bounds__(TB, 1) k_lstm(
    const int*   __restrict__ lengths,
    const float* __restrict__ Wih0, const float* __restrict__ Whh0, const float* __restrict__ bb0,
    const float* __restrict__ Wih1, const float* __restrict__ Whh1, const float* __restrict__ bb1,
    const float* __restrict__ Wih2, const float* __restrict__ Whh2, const float* __restrict__ bb2,
    const float* __restrict__ fcw,  const float* __restrict__ fcb,
    float* __restrict__ out)
{
    // smem: weights pre-splatted to f32x2: [k][r] for k in [0, Din+H), r = g*4+jj (16 rows)
    __shared__ unsigned long long sW[(HH + HH) * 16];  // 41984 B (max layer)
    __shared__ float sG[16 * 64];                       // gates [r][b]
    __shared__ float sC[JT * 64];                       // private cell state [jj][b]
    __shared__ float sB[16];                            // bias slice
    __shared__ int   sLen[BB];

    const int tid = threadIdx.x;
    const int cta = blockIdx.x;
    const int l   = cta / NCOL;
    const int cb  = cta - l * NCOL;
    const int j0  = cb * JT;

    const float *Wih, *Whh, *bias;
    int Din;
    if (l == 0)      { Wih = Wih0; Whh = Whh0; bias = bb0; Din = DD; }
    else if (l == 1) { Wih = Wih1; Whh = Whh1; bias = bb1; Din = HH; }
    else             { Wih = Wih2; Whh = Whh2; bias = bb2; Din = HH; }

    // Load weight slices (rows {g*H + j0 + jj}) transposed + splatted into smem
    for (int idx = tid; idx < Din * 16; idx += TB) {
        int k = idx >> 4, r = idx & 15;
        int g = r >> 2, jj = r & 3;
        sW[idx] = splat2(Wih[(g * HH + j0 + jj) * Din + k]);
    }
    for (int idx = tid; idx < HH * 16; idx += TB) {
        int k = idx >> 4, r = idx & 15;
        int g = r >> 2, jj = r & 3;
        sW[Din * 16 + idx] = splat2(Whh[(g * HH + j0 + jj) * HH + k]);
    }
    if (tid < 16) {
        int g = tid >> 2, jj = tid & 3;
        sB[tid] = bias[g * HH + j0 + jj];
    }
    if (tid < BB) sLen[tid] = lengths[tid];
    for (int idx = tid; idx < JT * 64; idx += TB) sC[idx] = 0.f;
    __syncthreads();

    const int lane = tid & 31;
    const int rg   = tid >> 5;        // 4 warps: each owns 4 gate-rows
    const int b0i  = lane * 2;        // batch pair
    const int r0   = rg * 4;
    const unsigned long long* sWh = sW + Din * 16;

    for (int s = 0; s <= TT + 1; ++s) {
        const int t = s - l;
        if (t >= 0 && t < TT) {
            const float* xin = (l == 0) ? (g_xT + t * DD * BB)
                                        : (g_h + ((l - 1) * 2 + (t & 1)) * HH * BB);
            const float* hin = g_h + (l * 2 + ((t + 1) & 1)) * HH * BB;

            unsigned long long a0 = splat2(sB[r0 + 0]);
            unsigned long long a1 = splat2(sB[r0 + 1]);
            unsigned long long a2 = splat2(sB[r0 + 2]);
            unsigned long long a3 = splat2(sB[r0 + 3]);

            const float* xp = xin + b0i;
            #pragma unroll 4
            for (int k = 0; k < Din; ++k) {
                unsigned long long xv = *(const unsigned long long*)(xp + k * BB);
                const ulonglong2* wp = (const ulonglong2*)(sW + k * 16 + r0);
                ulonglong2 wA = wp[0];
                ulonglong2 wB = wp[1];
                a0 = fma2(xv, wA.x, a0);
                a1 = fma2(xv, wA.y, a1);
                a2 = fma2(xv, wB.x, a2);
                a3 = fma2(xv, wB.y, a3);
            }
            const float* hp = hin + b0i;
            #pragma unroll 4
            for (int k = 0; k < HH; ++k) {
                unsigned long long xv = *(const unsigned long long*)(hp + k * BB);
                const ulonglong2* wp = (const ulonglong2*)(sWh + k * 16 + r0);
                ulonglong2 wA = wp[0];
                ulonglong2 wB = wp[1];
                a0 = fma2(xv, wA.x, a0);
                a1 = fma2(xv, wA.y, a1);
                a2 = fma2(xv, wB.x, a2);
                a3 = fma2(xv, wB.y, a3);
            }
            *(float2*)&sG[(r0 + 0) * 64 + b0i] = make_float2(lo2(a0), hi2(a0));
            *(float2*)&sG[(r0 + 1) * 64 + b0i] = make_float2(lo2(a1), hi2(a1));
            *(float2*)&sG[(r0 + 2) * 64 + b0i] = make_float2(lo2(a2), hi2(a2));
            *(float2*)&sG[(r0 + 3) * 64 + b0i] = make_float2(lo2(a3), hi2(a3));
            __syncthreads();

            float* hout = g_h + (l * 2 + (t & 1)) * HH * BB;
            #pragma unroll
            for (int rep = 0; rep < 2; ++rep) {
                int it = tid + rep * TB;
                int b = it & 63, jj = it >> 6;
                float iv = sG[(0  + jj) * 64 + b];
                float fv = sG[(4  + jj) * 64 + b];
                float gv = sG[(8  + jj) * 64 + b];
                float ov = sG[(12 + jj) * 64 + b];
                float co = sC[jj * 64 + b];
                float ig = 1.f / (1.f + expf(-iv));
                float fg = 1.f / (1.f + expf(-fv));
                float og = 1.f / (1.f + expf(-ov));
                float cn = fg * co + ig * tanhf(gv);
                float hn = og * tanhf(cn);
                bool  m  = (t < sLen[b]);
                int   j  = j0 + jj;
                float hpv = hin[j * BB + b];     // frozen value if past length
                sC[jj * 64 + b]    = m ? cn : co;
                hout[j * BB + b]   = m ? hn : hpv;
            }
        }

        // ---- software grid barrier (all 123 CTAs, every wavefront step) ----
        __syncthreads();
        if (tid == 0) {
            __threadfence();  // make our h writes visible
            const unsigned phase  = (unsigned)(s + 1);
            const unsigned target = (unsigned)NCTA * phase;
            unsigned v = atomicAdd(&g_cnt, 1u) + 1u;
            if (v == target) {
                atomicExch(&g_rel, phase);
            } else {
                unsigned r;
                while (true) {
                    asm volatile("ld.global.acquire.gpu.u32 %0, [%1];"
                                 : "=r"(r) : "l"(&g_rel));
                    if (r >= phase) break;
                    __nanosleep(64);
                }
            }
            __threadfence();  // gpu-scope fence -> CCTL.IVALL: invalidate L1 for fresh h reads
        }
        __syncthreads();
    }

    // ---- final FC on CTA 0: out[b][o] = h2_final[.,b] . fcw[o,.] + fcb[o] ----
    if (cta == 0) {
        const float* h2 = g_h + (2 * 2 + ((TT - 1) & 1)) * HH * BB;
        for (int it = tid; it < BB * NOUT; it += TB) {
            int b = it / NOUT, o = it - b * NOUT;
            float acc = fcb[o];
            #pragma unroll 4
            for (int j = 0; j < HH; ++j)
                acc += h2[j * BB + b] * fcw[o * HH + j];
            out[b * NOUT + o] = acc;
        }
    }
}

// ---------------- launch ----------------
extern "C" void kernel_launch(void* const* d_in, const int* in_sizes, int n_in,
                              void* d_out, int out_size) {
    const float* x       = (const float*)d_in[0];
    const int*   lengths = (const int*)  d_in[1];
    const float* Wih0    = (const float*)d_in[2];
    const float* Whh0    = (const float*)d_in[3];
    const float* b0      = (const float*)d_in[4];
    const float* Wih1    = (const float*)d_in[5];
    const float* Whh1    = (const float*)d_in[6];
    const float* b1      = (const float*)d_in[7];
    const float* Wih2    = (const float*)d_in[8];
    const float* Whh2    = (const float*)d_in[9];
    const float* b2      = (const float*)d_in[10];
    const float* fcw     = (const float*)d_in[11];
    const float* fcb     = (const float*)d_in[12];
    float* out = (float*)d_out;

    k_init<<<64, 256>>>();
    k_transpose<<<TT, 256>>>(x);
    k_lstm<<<NCTA, TB>>>(lengths,
                         Wih0, Whh0, b0,
                         Wih1, Whh1, b1,
                         Wih2, Whh2, b2,
                         fcw, fcb, out);
}

// round 2
// speedup vs baseline: 2.3346x; 2.3346x over previous
#include <cuda_runtime.h>
#include <math.h>

// Problem constants
#define BB     64
#define TT     2048
#define DD     40
#define HH     164
#define NOUT   7
#define JT     4               // hidden columns per CTA
#define NCOL   (HH / JT)       // 41 CTAs per layer
#define NLAYER 3
#define NCTA   (NCOL * NLAYER) // 123 CTAs (< 148 SMs -> co-resident at 1 CTA/SM)
#define TB     128
#define KMAX   (HH + HH)       // 328 (max Din+H)

// ---- dynamic smem layout (bytes) ----
#define OFF_W   0
#define SZ_W    (KMAX * 16 * 8)            // splatted weights: 41984
#define OFF_X   (OFF_W + SZ_W)
#define SZ_X    (KMAX * BB * 4)            // staged [x;h]: 83968
#define OFF_G   (OFF_X + SZ_X)
#define SZ_G    (16 * BB * 4)              // gates
#define OFF_C   (OFF_G + SZ_G)
#define SZ_C    (JT * BB * 4)              // cell state
#define OFF_B   (OFF_C + SZ_C)
#define SZ_B    (16 * 4)
#define OFF_L   (OFF_B + SZ_B)
#define SZ_L    (BB * 4)
#define SMEM_BYTES (OFF_L + SZ_L)          // ~131 KB

// ---------------- device scratch ----------------
__device__ float    g_xT[TT * DD * BB];            // x transposed: [t][d][b]
__device__ float    g_h[NLAYER * 2 * HH * BB];     // h ring: [l][parity][j][b]
__device__ volatile unsigned g_flag[NCTA * 32];    // per-CTA step flags, 128B apart

// ---------------- helpers ----------------
__device__ __forceinline__ unsigned long long fma2(unsigned long long a,
                                                   unsigned long long b,
                                                   unsigned long long c) {
    unsigned long long d;
    asm("fma.rn.f32x2 %0, %1, %2, %3;" : "=l"(d) : "l"(a), "l"(b), "l"(c));
    return d;
}
__device__ __forceinline__ unsigned long long splat2(float w) {
    unsigned long long v = (unsigned long long)__float_as_uint(w);
    return v | (v << 32);
}
__device__ __forceinline__ float lo2(unsigned long long v) { return __uint_as_float((unsigned)v); }
__device__ __forceinline__ float hi2(unsigned long long v) { return __uint_as_float((unsigned)(v >> 32)); }

// ---------------- init ----------------
__global__ void k_init() {
    const int n = NLAYER * 2 * HH * BB;
    for (int i = blockIdx.x * blockDim.x + threadIdx.x; i < n; i += gridDim.x * blockDim.x)
        g_h[i] = 0.f;
    int gi = blockIdx.x * blockDim.x + threadIdx.x;
    if (gi < NCTA * 32) g_flag[gi] = 0u;
}

// ---------------- transpose x[B][T][D] -> g_xT[t][d][b] ----------------
__global__ void k_transpose(const float* __restrict__ x) {
    __shared__ float s[BB * DD];
    const int t = blockIdx.x;
    for (int idx = threadIdx.x; idx < BB * DD; idx += blockDim.x) {
        int b = idx / DD, d = idx - b * DD;
        s[idx] = x[(b * TT + t) * DD + d];
    }
    __syncthreads();
    for (int idx = threadIdx.x; idx < BB * DD; idx += blockDim.x) {
        int d = idx >> 6, b = idx & 63;
        g_xT[t * DD * BB + idx] = s[b * DD + d];
    }
}

// ---------------- persistent wavefront LSTM ----------------
__global__ void __launch_bounds__(TB, 1) k_lstm(
    const int*   __restrict__ lengths,
    const float* __restrict__ Wih0, const float* __restrict__ Whh0, const float* __restrict__ bb0,
    const float* __restrict__ Wih1, const float* __restrict__ Whh1, const float* __restrict__ bb1,
    const float* __restrict__ Wih2, const float* __restrict__ Whh2, const float* __restrict__ bb2,
    const float* __restrict__ fcw,  const float* __restrict__ fcb,
    float* __restrict__ out)
{
    extern __shared__ unsigned char smem[];
    unsigned long long* sW = (unsigned long long*)(smem + OFF_W);
    float* sX   = (float*)(smem + OFF_X);
    float* sG   = (float*)(smem + OFF_G);
    float* sC   = (float*)(smem + OFF_C);
    float* sB   = (float*)(smem + OFF_B);
    int*   sLen = (int*)  (smem + OFF_L);

    const int tid = threadIdx.x;
    const int cta = blockIdx.x;
    const int l   = cta / NCOL;
    const int cb  = cta - l * NCOL;
    const int j0  = cb * JT;

    const float *Wih, *Whh, *bias;
    int Din;
    if (l == 0)      { Wih = Wih0; Whh = Whh0; bias = bb0; Din = DD; }
    else if (l == 1) { Wih = Wih1; Whh = Whh1; bias = bb1; Din = HH; }
    else             { Wih = Wih2; Whh = Whh2; bias = bb2; Din = HH; }
    const int KTOT = Din + HH;

    // Pre-splat weight slices into smem: sW[k][r], r = g*4+jj, k = [x rows ; h rows]
    for (int idx = tid; idx < Din * 16; idx += TB) {
        int k = idx >> 4, r = idx & 15;
        int g = r >> 2, jj = r & 3;
        sW[k * 16 + r] = splat2(Wih[(g * HH + j0 + jj) * Din + k]);
    }
    for (int idx = tid; idx < HH * 16; idx += TB) {
        int k = idx >> 4, r = idx & 15;
        int g = r >> 2, jj = r & 3;
        sW[(Din + k) * 16 + r] = splat2(Whh[(g * HH + j0 + jj) * HH + k]);
    }
    if (tid < 16) {
        int g = tid >> 2, jj = tid & 3;
        sB[tid] = bias[g * HH + j0 + jj];
    }
    if (tid < BB) sLen[tid] = lengths[tid];
    for (int idx = tid; idx < JT * BB; idx += TB) sC[idx] = 0.f;
    __syncthreads();

    const int lane = tid & 31;
    const int rg   = tid >> 5;     // warp -> 4 gate-rows
    const int b0i  = lane * 2;     // batch pair
    const int r0   = rg * 4;

    for (int s = 0; s <= TT + 1; ++s) {
        const int t = s - l;
        const unsigned phase = (unsigned)(s + 1);

        if (t >= 0 && t < TT) {
            // ---- stage [x;h] into smem with L1-bypassing loads ----
            const float* xin = (l == 0) ? (g_xT + t * DD * BB)
                                        : (g_h + ((l - 1) * 2 + (t & 1)) * HH * BB);
            const float* hin = g_h + (l * 2 + ((t + 1) & 1)) * HH * BB;
            const int nx = Din * BB;
            for (int i = tid * 4; i < nx; i += TB * 4) {
                float4 v = __ldcv((const float4*)(xin + i));
                *(float4*)(sX + i) = v;
            }
            for (int i = tid * 4; i < HH * BB; i += TB * 4) {
                float4 v = __ldcv((const float4*)(hin + i));
                *(float4*)(sX + nx + i) = v;
            }
            __syncthreads();

            // ---- gate GEMM: all-smem, f32x2 ----
            unsigned long long a0 = splat2(sB[r0 + 0]);
            unsigned long long a1 = splat2(sB[r0 + 1]);
            unsigned long long a2 = splat2(sB[r0 + 2]);
            unsigned long long a3 = splat2(sB[r0 + 3]);

            const float* xp = sX + b0i;
            #pragma unroll 4
            for (int k = 0; k < KTOT; ++k) {
                unsigned long long xv = *(const unsigned long long*)(xp + k * BB);
                const ulonglong2* wp = (const ulonglong2*)(sW + k * 16 + r0);
                ulonglong2 wA = wp[0];
                ulonglong2 wB = wp[1];
                a0 = fma2(xv, wA.x, a0);
                a1 = fma2(xv, wA.y, a1);
                a2 = fma2(xv, wB.x, a2);
                a3 = fma2(xv, wB.y, a3);
            }
            *(float2*)&sG[(r0 + 0) * BB + b0i] = make_float2(lo2(a0), hi2(a0));
            *(float2*)&sG[(r0 + 1) * BB + b0i] = make_float2(lo2(a1), hi2(a1));
            *(float2*)&sG[(r0 + 2) * BB + b0i] = make_float2(lo2(a2), hi2(a2));
            *(float2*)&sG[(r0 + 3) * BB + b0i] = make_float2(lo2(a3), hi2(a3));
            __syncthreads();

            // ---- elementwise + state update ----
            float* hout = g_h + (l * 2 + (t & 1)) * HH * BB;
            #pragma unroll
            for (int rep = 0; rep < 2; ++rep) {
                int it = tid + rep * TB;
                int b = it & 63, jj = it >> 6;
                float iv = sG[(0  + jj) * BB + b];
                float fv = sG[(4  + jj) * BB + b];
                float gv = sG[(8  + jj) * BB + b];
                float ov = sG[(12 + jj) * BB + b];
                float co = sC[jj * BB + b];
                float ig = 1.f / (1.f + expf(-iv));
                float fg = 1.f / (1.f + expf(-fv));
                float og = 1.f / (1.f + expf(-ov));
                float cn = fg * co + ig * tanhf(gv);
                float hn = og * tanhf(cn);
                bool  m  = (t < sLen[b]);
                int   j  = j0 + jj;
                float hpv = sX[(Din + j) * BB + b];   // frozen value if past length
                sC[jj * BB + b]  = m ? cn : co;
                hout[j * BB + b] = m ? hn : hpv;
            }
        }

        // ---- distributed flag barrier (no atomic serialization) ----
        __syncthreads();
        if (tid == 0) {
            __threadfence();          // make this CTA's h writes visible at gpu scope
            g_flag[cta * 32] = phase; // volatile store
        }
        if (tid < NCTA) {
            while (g_flag[tid * 32] < phase) { __nanosleep(32); }
        }
        __syncthreads();
    }

    // ---- final FC on CTA 0 (L1-bypassing reads of h2) ----
    if (cta == 0) {
        const float* h2 = g_h + (2 * 2 + ((TT - 1) & 1)) * HH * BB;
        for (int it = tid; it < BB * NOUT; it += TB) {
            int b = it / NOUT, o = it - b * NOUT;
            float acc = fcb[o];
            #pragma unroll 4
            for (int j = 0; j < HH; ++j)
                acc += __ldcv(h2 + j * BB + b) * fcw[o * HH + j];
            out[b * NOUT + o] = acc;
        }
    }
}

// ---------------- launch ----------------
extern "C" void kernel_launch(void* const* d_in, const int* in_sizes, int n_in,
                              void* d_out, int out_size) {
    const float* x       = (const float*)d_in[0];
    const int*   lengths = (const int*)  d_in[1];
    const float* Wih0    = (const float*)d_in[2];
    const float* Whh0    = (const float*)d_in[3];
    const float* b0      = (const float*)d_in[4];
    const float* Wih1    = (const float*)d_in[5];
    const float* Whh1    = (const float*)d_in[6];
    const float* b1      = (const float*)d_in[7];
    const float* Wih2    = (const float*)d_in[8];
    const float* Whh2    = (const float*)d_in[9];
    const float* b2      = (const float*)d_in[10];
    const float* fcw     = (const float*)d_in[11];
    const float* fcb     = (const float*)d_in[12];
    float* out = (float*)d_out;

    static bool attr_set = false;
    if (!attr_set) {
        cudaFuncSetAttribute(k_lstm, cudaFuncAttributeMaxDynamicSharedMemorySize, SMEM_BYTES);
        attr_set = true;
    }

    k_init<<<64, 256>>>();
    k_transpose<<<TT, 256>>>(x);
    k_lstm<<<NCTA, TB, SMEM_BYTES>>>(lengths,
                                     Wih0, Whh0, b0,
                                     Wih1, Whh1, b1,
                                     Wih2, Whh2, b2,
                                     fcw, fcb, out);
}

// round 3
// speedup vs baseline: 2.9379x; 1.2584x over previous
#include <cuda_runtime.h>
#include <math.h>

// Problem constants
#define BB     64
#define TT     2048
#define DD     40
#define HH     164
#define NOUT   7
#define JT     4               // hidden columns per CTA
#define NCOL   (HH / JT)       // 41 CTAs per layer
#define NLAYER 3
#define NCTA   (NCOL * NLAYER) // 123 CTAs (< 148 SMs -> co-resident)
#define TB     256             // 8 warps: 2 warp-groups k-split
#define KMAX   (HH + HH)       // 328

// ---- dynamic smem layout (bytes) ----
#define OFF_W   0
#define SZ_W    (KMAX * 16 * 8)            // splatted weights: 41984
#define OFF_X   (OFF_W + SZ_W)
#define SZ_X    (KMAX * BB * 4)            // staged [x;h]: 83968
#define OFF_P   (OFF_X + SZ_X)
#define SZ_P    (2 * 16 * BB * 4)          // k-split partials: 8192
#define OFF_C   (OFF_P + SZ_P)
#define SZ_C    (JT * BB * 4)
#define OFF_B   (OFF_C + SZ_C)
#define SZ_B    (16 * 4)
#define OFF_L   (OFF_B + SZ_B)
#define SZ_L    (BB * 4)
#define SMEM_BYTES (OFF_L + SZ_L)          // ~135 KB

// ---------------- device scratch ----------------
__device__ float    g_xT[TT * DD * BB];            // x transposed: [t][d][b]
__device__ float    g_h[NLAYER * 2 * HH * BB];     // h ring: [l][parity][j][b]
__device__ volatile unsigned g_flag[NCTA * 32];    // per-CTA step flags, 128B apart

// ---------------- helpers ----------------
__device__ __forceinline__ unsigned long long fma2(unsigned long long a,
                                                   unsigned long long b,
                                                   unsigned long long c) {
    unsigned long long d;
    asm("fma.rn.f32x2 %0, %1, %2, %3;" : "=l"(d) : "l"(a), "l"(b), "l"(c));
    return d;
}
__device__ __forceinline__ unsigned long long splat2(float w) {
    unsigned long long v = (unsigned long long)__float_as_uint(w);
    return v | (v << 32);
}
__device__ __forceinline__ float lo2(unsigned long long v) { return __uint_as_float((unsigned)v); }
__device__ __forceinline__ float hi2(unsigned long long v) { return __uint_as_float((unsigned)(v >> 32)); }

__device__ __forceinline__ void cp16(float* dst_smem, const float4* src) {
    unsigned sa = (unsigned)__cvta_generic_to_shared(dst_smem);
    asm volatile("cp.async.cg.shared.global [%0], [%1], 16;" :: "r"(sa), "l"(src));
}

// ---------------- init ----------------
__global__ void k_init() {
    const int n = NLAYER * 2 * HH * BB;
    for (int i = blockIdx.x * blockDim.x + threadIdx.x; i < n; i += gridDim.x * blockDim.x)
        g_h[i] = 0.f;
    int gi = blockIdx.x * blockDim.x + threadIdx.x;
    if (gi < NCTA * 32) g_flag[gi] = 0u;
}

// ---------------- transpose x[B][T][D] -> g_xT[t][d][b] ----------------
__global__ void k_transpose(const float* __restrict__ x) {
    __shared__ float s[BB * DD];
    const int t = blockIdx.x;
    for (int idx = threadIdx.x; idx < BB * DD; idx += blockDim.x) {
        int b = idx / DD, d = idx - b * DD;
        s[idx] = x[(b * TT + t) * DD + d];
    }
    __syncthreads();
    for (int idx = threadIdx.x; idx < BB * DD; idx += blockDim.x) {
        int d = idx >> 6, b = idx & 63;
        g_xT[t * DD * BB + idx] = s[b * DD + d];
    }
}

// ---------------- persistent wavefront LSTM ----------------
__global__ void __launch_bounds__(TB, 1) k_lstm(
    const int*   __restrict__ lengths,
    const float* __restrict__ Wih0, const float* __restrict__ Whh0, const float* __restrict__ bb0,
    const float* __restrict__ Wih1, const float* __restrict__ Whh1, const float* __restrict__ bb1,
    const float* __restrict__ Wih2, const float* __restrict__ Whh2, const float* __restrict__ bb2,
    const float* __restrict__ fcw,  const float* __restrict__ fcb,
    float* __restrict__ out)
{
    extern __shared__ unsigned char smem[];
    unsigned long long* sW = (unsigned long long*)(smem + OFF_W);
    float* sX   = (float*)(smem + OFF_X);
    float* sP   = (float*)(smem + OFF_P);
    float* sC   = (float*)(smem + OFF_C);
    float* sB   = (float*)(smem + OFF_B);
    int*   sLen = (int*)  (smem + OFF_L);

    const int tid = threadIdx.x;
    const int cta = blockIdx.x;
    const int l   = cta / NCOL;
    const int cb  = cta - l * NCOL;
    const int j0  = cb * JT;

    const float *Wih, *Whh, *bias;
    int Din;
    if (l == 0)      { Wih = Wih0; Whh = Whh0; bias = bb0; Din = DD; }
    else if (l == 1) { Wih = Wih1; Whh = Whh1; bias = bb1; Din = HH; }
    else             { Wih = Wih2; Whh = Whh2; bias = bb2; Din = HH; }
    const int KTOT = Din + HH;
    const int QR   = (KTOT + 3) >> 2;   // rows per staging chunk
    const int NF4  = KTOT * 16;         // total float4 count of [x;h]

    // Pre-splat weight slices into smem: sW[k][r], r = g*4+jj
    for (int idx = tid; idx < Din * 16; idx += TB) {
        int k = idx >> 4, r = idx & 15;
        int g = r >> 2, jj = r & 3;
        sW[k * 16 + r] = splat2(Wih[(g * HH + j0 + jj) * Din + k]);
    }
    for (int idx = tid; idx < HH * 16; idx += TB) {
        int k = idx >> 4, r = idx & 15;
        int g = r >> 2, jj = r & 3;
        sW[(Din + k) * 16 + r] = splat2(Whh[(g * HH + j0 + jj) * HH + k]);
    }
    if (tid < 16) {
        int g = tid >> 2, jj = tid & 3;
        sB[tid] = bias[g * HH + j0 + jj];
    }
    if (tid < BB) sLen[tid] = lengths[tid];
    if (tid < JT * BB) sC[tid] = 0.f;
    __syncthreads();

    const int lane = tid & 31;
    const int warp = tid >> 5;
    const int wg   = warp >> 2;         // k-split warp-group: 0 or 1
    const int rg   = warp & 3;          // 4 gate-rows per warp
    const int b0i  = lane * 2;
    const int r0   = rg * 4;
    float4* sX4 = (float4*)sX;

    for (int s = 0; s <= TT + 1; ++s) {
        const int t = s - l;
        const unsigned phase = (unsigned)(s + 1);

        if (t >= 0 && t < TT) {
            const float* xin = (l == 0) ? (g_xT + t * DD * BB)
                                        : (g_h + ((l - 1) * 2 + (t & 1)) * HH * BB);
            const float* hin = g_h + (l * 2 + ((t + 1) & 1)) * HH * BB;
            const float4* xin4 = (const float4*)xin;
            const float4* hin4 = (const float4*)hin;
            const int hbase = Din * 16;

            // stage chunk 0
            {
                int i1 = min(QR * 16, NF4);
                for (int i = tid; i < i1; i += TB) {
                    int row = i >> 4;
                    cp16(sX + i * 4, (row < Din) ? (xin4 + i) : (hin4 + (i - hbase)));
                }
                asm volatile("cp.async.commit_group;");
            }

            unsigned long long a0, a1, a2, a3;
            if (wg == 0) {
                a0 = splat2(sB[r0 + 0]); a1 = splat2(sB[r0 + 1]);
                a2 = splat2(sB[r0 + 2]); a3 = splat2(sB[r0 + 3]);
            } else {
                a0 = a1 = a2 = a3 = 0ull;
            }

            #pragma unroll
            for (int c = 0; c < 4; ++c) {
                if (c < 3) {
                    int i0 = (c + 1) * QR * 16;
                    int i1 = min(i0 + QR * 16, NF4);
                    for (int i = i0 + tid; i < i1; i += TB) {
                        int row = i >> 4;
                        cp16(sX + i * 4, (row < Din) ? (xin4 + i) : (hin4 + (i - hbase)));
                    }
                    asm volatile("cp.async.commit_group;");
                    asm volatile("cp.async.wait_group 1;");
                } else {
                    asm volatile("cp.async.wait_group 0;");
                }
                __syncthreads();

                const int kb = c * QR;
                const int ke = min(kb + QR, KTOT);
                const int mid = kb + ((ke - kb + 1) >> 1);
                const int k0 = wg ? mid : kb;
                const int k1 = wg ? ke  : mid;

                const float* xp = sX + b0i;
                #pragma unroll 4
                for (int k = k0; k < k1; ++k) {
                    unsigned long long xv = *(const unsigned long long*)(xp + k * BB);
                    const ulonglong2* wp = (const ulonglong2*)(sW + k * 16 + r0);
                    ulonglong2 wA = wp[0];
                    ulonglong2 wB = wp[1];
                    a0 = fma2(xv, wA.x, a0);
                    a1 = fma2(xv, wA.y, a1);
                    a2 = fma2(xv, wB.x, a2);
                    a3 = fma2(xv, wB.y, a3);
                }
            }

            // write k-split partials
            float* pp = sP + wg * (16 * BB);
            *(float2*)&pp[(r0 + 0) * BB + b0i] = make_float2(lo2(a0), hi2(a0));
            *(float2*)&pp[(r0 + 1) * BB + b0i] = make_float2(lo2(a1), hi2(a1));
            *(float2*)&pp[(r0 + 2) * BB + b0i] = make_float2(lo2(a2), hi2(a2));
            *(float2*)&pp[(r0 + 3) * BB + b0i] = make_float2(lo2(a3), hi2(a3));
            __syncthreads();

            // ---- elementwise + state update: 1 item/thread ----
            {
                float* hout = g_h + (l * 2 + (t & 1)) * HH * BB;
                int b = tid & 63, jj = tid >> 6;
                float iv = sP[(0  + jj) * BB + b] + sP[16 * BB + (0  + jj) * BB + b];
                float fv = sP[(4  + jj) * BB + b] + sP[16 * BB + (4  + jj) * BB + b];
                float gv = sP[(8  + jj) * BB + b] + sP[16 * BB + (8  + jj) * BB + b];
                float ov = sP[(12 + jj) * BB + b] + sP[16 * BB + (12 + jj) * BB + b];
                float co = sC[jj * BB + b];
                float ig = 1.f / (1.f + expf(-iv));
                float fg = 1.f / (1.f + expf(-fv));
                float og = 1.f / (1.f + expf(-ov));
                float cn = fg * co + ig * tanhf(gv);
                float hn = og * tanhf(cn);
                bool  m  = (t < sLen[b]);
                int   j  = j0 + jj;
                float hpv = sX[(Din + j) * BB + b];   // frozen value if past length
                sC[jj * BB + b]  = m ? cn : co;
                hout[j * BB + b] = m ? hn : hpv;
            }
        }

        // ---- distributed flag barrier ----
        __syncthreads();
        if (tid == 0) {
            __threadfence();          // publish this CTA's h writes (gpu scope)
            g_flag[cta * 32] = phase;
        }
        if (tid < NCTA) {
            while (g_flag[tid * 32] < phase) { __nanosleep(20); }
        }
        __syncthreads();
    }

    // ---- final FC on CTA 0 (L1-bypassing reads of h2) ----
    if (cta == 0) {
        const float* h2 = g_h + (2 * 2 + ((TT - 1) & 1)) * HH * BB;
        for (int it = tid; it < BB * NOUT; it += TB) {
            int b = it / NOUT, o = it - b * NOUT;
            float acc = fcb[o];
            #pragma unroll 4
            for (int j = 0; j < HH; ++j)
                acc += __ldcv(h2 + j * BB + b) * fcw[o * HH + j];
            out[b * NOUT + o] = acc;
        }
    }
}

// ---------------- launch ----------------
extern "C" void kernel_launch(void* const* d_in, const int* in_sizes, int n_in,
                              void* d_out, int out_size) {
    const float* x       = (const float*)d_in[0];
    const int*   lengths = (const int*)  d_in[1];
    const float* Wih0    = (const float*)d_in[2];
    const float* Whh0    = (const float*)d_in[3];
    const float* b0      = (const float*)d_in[4];
    const float* Wih1    = (const float*)d_in[5];
    const float* Whh1    = (const float*)d_in[6];
    const float* b1      = (const float*)d_in[7];
    const float* Wih2    = (const float*)d_in[8];
    const float* Whh2    = (const float*)d_in[9];
    const float* b2      = (const float*)d_in[10];
    const float* fcw     = (const float*)d_in[11];
    const float* fcb     = (const float*)d_in[12];
    float* out = (float*)d_out;

    static bool attr_set = false;
    if (!attr_set) {
        cudaFuncSetAttribute(k_lstm, cudaFuncAttributeMaxDynamicSharedMemorySize, SMEM_BYTES);
        attr_set = true;
    }

    k_init<<<64, 256>>>();
    k_transpose<<<TT, 256>>>(x);
    k_lstm<<<NCTA, TB, SMEM_BYTES>>>(lengths,
                                     Wih0, Whh0, b0,
                                     Wih1, Whh1, b1,
                                     Wih2, Whh2, b2,
                                     fcw, fcb, out);
}

// round 4
// speedup vs baseline: 3.7367x; 1.2719x over previous
#include <cuda_runtime.h>
#include <math.h>

// Problem constants
#define BB     64
#define TT     2048
#define DD     40
#define HH     164
#define NOUT   7
#define JT     4               // hidden columns per CTA
#define NCOL   (HH / JT)       // 41 CTAs per layer
#define NLAYER 3
#define NCTA   (NCOL * NLAYER) // 123 CTAs (< 148 SMs -> co-resident)
#define TB     256             // 8 warps
#define KMAX   (HH + HH)       // 328
#define NCHUNK 4

// ---- dynamic smem layout (bytes) ----
#define OFF_W   0
#define SZ_W    (KMAX * 16 * 8)            // splatted weights: 41984
#define OFF_X   (OFF_W + SZ_W)
#define SZ_X    (KMAX * BB * 4)            // staged [x;h]: 83968
#define OFF_P   (OFF_X + SZ_X)
#define SZ_P    (NCHUNK * 16 * BB * 4)     // k-split partials: 16384
#define OFF_C   (OFF_P + SZ_P)
#define SZ_C    (JT * BB * 4)
#define OFF_B   (OFF_C + SZ_C)
#define SZ_B    (16 * 4)
#define OFF_L   (OFF_B + SZ_B)
#define SZ_L    (BB * 4)
#define OFF_M   (OFF_L + SZ_L)             // mbarriers
#define SZ_M    (NCHUNK * 8)
#define SMEM_BYTES (OFF_M + SZ_M)          // ~140.4 KB

// ---------------- device scratch ----------------
__device__ __align__(256) float g_xT[TT * DD * BB];         // x transposed: [t][d][b]
__device__ __align__(256) float g_h[NLAYER * 2 * HH * BB];  // h ring: [l][parity][j][b]
__device__ unsigned g_flag[NCTA * 32];                      // per-CTA step flags, 128B apart

// ---------------- helpers ----------------
__device__ __forceinline__ unsigned long long fma2(unsigned long long a,
                                                   unsigned long long b,
                                                   unsigned long long c) {
    unsigned long long d;
    asm("fma.rn.f32x2 %0, %1, %2, %3;" : "=l"(d) : "l"(a), "l"(b), "l"(c));
    return d;
}
__device__ __forceinline__ unsigned long long splat2(float w) {
    unsigned long long v = (unsigned long long)__float_as_uint(w);
    return v | (v << 32);
}
__device__ __forceinline__ void bulk_g2s(void* dst_smem, const void* src, int bytes, unsigned mbar) {
    unsigned d = (unsigned)__cvta_generic_to_shared(dst_smem);
    asm volatile("cp.async.bulk.shared::cluster.global.mbarrier::complete_tx::bytes [%0], [%1], %2, [%3];"
                 :: "r"(d), "l"(src), "r"(bytes), "r"(mbar) : "memory");
}
__device__ __forceinline__ void mbar_init(unsigned addr, unsigned cnt) {
    asm volatile("mbarrier.init.shared.b64 [%0], %1;" :: "r"(addr), "r"(cnt) : "memory");
}
__device__ __forceinline__ void mbar_expect_tx(unsigned addr, unsigned bytes) {
    asm volatile("mbarrier.arrive.expect_tx.shared.b64 _, [%0], %1;" :: "r"(addr), "r"(bytes) : "memory");
}
__device__ __forceinline__ void mbar_wait(unsigned addr, unsigned parity) {
    asm volatile(
        "{\n\t"
        ".reg .pred P1;\n\t"
        "WAIT_%=:\n\t"
        "mbarrier.try_wait.parity.acquire.cta.shared::cta.b64 P1, [%0], %1, 0x989680;\n\t"
        "@P1 bra DONE_%=;\n\t"
        "bra WAIT_%=;\n\t"
        "DONE_%=:\n\t"
        "}"
        :: "r"(addr), "r"(parity) : "memory");
}

// ---------------- init ----------------
__global__ void k_init() {
    const int n = NLAYER * 2 * HH * BB;
    for (int i = blockIdx.x * blockDim.x + threadIdx.x; i < n; i += gridDim.x * blockDim.x)
        g_h[i] = 0.f;
    int gi = blockIdx.x * blockDim.x + threadIdx.x;
    if (gi < NCTA * 32) g_flag[gi] = 0u;
}

// ---------------- transpose x[B][T][D] -> g_xT[t][d][b] ----------------
__global__ void k_transpose(const float* __restrict__ x) {
    __shared__ float s[BB * DD];
    const int t = blockIdx.x;
    for (int idx = threadIdx.x; idx < BB * DD; idx += blockDim.x) {
        int b = idx / DD, d = idx - b * DD;
        s[idx] = x[(b * TT + t) * DD + d];
    }
    __syncthreads();
    for (int idx = threadIdx.x; idx < BB * DD; idx += blockDim.x) {
        int d = idx >> 6, b = idx & 63;
        g_xT[t * DD * BB + idx] = s[b * DD + d];
    }
}

// ---------------- persistent wavefront LSTM ----------------
__global__ void __launch_bounds__(TB, 1) k_lstm(
    const int*   __restrict__ lengths,
    const float* __restrict__ Wih0, const float* __restrict__ Whh0, const float* __restrict__ bb0,
    const float* __restrict__ Wih1, const float* __restrict__ Whh1, const float* __restrict__ bb1,
    const float* __restrict__ Wih2, const float* __restrict__ Whh2, const float* __restrict__ bb2,
    const float* __restrict__ fcw,  const float* __restrict__ fcb,
    float* __restrict__ out)
{
    extern __shared__ unsigned char smem[];
    unsigned long long* sW = (unsigned long long*)(smem + OFF_W);
    float* sX   = (float*)(smem + OFF_X);
    float* sP   = (float*)(smem + OFF_P);
    float* sC   = (float*)(smem + OFF_C);
    float* sB   = (float*)(smem + OFF_B);
    int*   sLen = (int*)  (smem + OFF_L);
    unsigned mb0 = (unsigned)__cvta_generic_to_shared(smem + OFF_M);

    const int tid = threadIdx.x;
    const int cta = blockIdx.x;
    const int l   = cta / NCOL;
    const int cb  = cta - l * NCOL;
    const int j0  = cb * JT;

    const float *Wih, *Whh, *bias;
    int Din;
    if (l == 0)      { Wih = Wih0; Whh = Whh0; bias = bb0; Din = DD; }
    else if (l == 1) { Wih = Wih1; Whh = Whh1; bias = bb1; Din = HH; }
    else             { Wih = Wih2; Whh = Whh2; bias = bb2; Din = HH; }
    const int KTOT = Din + HH;
    const int Q    = (KTOT + NCHUNK - 1) / NCHUNK;   // k-rows per chunk

    // Pre-splat weight slices into smem: sW[k][r], r = g*4+jj
    for (int idx = tid; idx < Din * 16; idx += TB) {
        int k = idx >> 4, r = idx & 15;
        int g = r >> 2, jj = r & 3;
        sW[k * 16 + r] = splat2(Wih[(g * HH + j0 + jj) * Din + k]);
    }
    for (int idx = tid; idx < HH * 16; idx += TB) {
        int k = idx >> 4, r = idx & 15;
        int g = r >> 2, jj = r & 3;
        sW[(Din + k) * 16 + r] = splat2(Whh[(g * HH + j0 + jj) * HH + k]);
    }
    if (tid < 16) {
        int g = tid >> 2, jj = tid & 3;
        sB[tid] = bias[g * HH + j0 + jj];
    }
    if (tid < BB) sLen[tid] = lengths[tid];
    if (tid < JT * BB) sC[tid] = 0.f;
    if (tid == 0) {
        #pragma unroll
        for (int c = 0; c < NCHUNK; ++c) mbar_init(mb0 + c * 8, 1);
    }
    __syncthreads();

    const int lane = tid & 31;
    const int warp = tid >> 5;
    const int kg   = warp >> 1;             // k-chunk group 0..3
    const int r0   = (warp & 1) * 8 + (lane >> 4) * 4;  // 4 rows starting here
    const int b0i  = (lane & 15) * 4;       // 4 batches per lane
    const int kb   = kg * Q;

    for (int s = 0; s <= TT + 1; ++s) {
        const int t = s - l;
        const unsigned phase = (unsigned)(s + 1);

        if (t >= 0 && t < TT) {
            const float* xin = (l == 0) ? (g_xT + t * DD * BB)
                                        : (g_h + ((l - 1) * 2 + (t & 1)) * HH * BB);
            const float* hin = g_h + (l * 2 + ((t + 1) & 1)) * HH * BB;
            const unsigned par = (unsigned)(t & 1);

            // ---- elected thread issues all chunk copies (bulk async + mbarrier) ----
            if (tid == 0) {
                #pragma unroll
                for (int c = 0; c < NCHUNK; ++c) {
                    int rb = c * Q;
                    int re = min(rb + Q, KTOT);
                    if (re <= rb) { mbar_expect_tx(mb0 + c * 8, 0); continue; }
                    mbar_expect_tx(mb0 + c * 8, (unsigned)((re - rb) * BB * 4));
                    int xr = min(Din, re) - rb;          // rows from xin
                    if (xr > 0)
                        bulk_g2s(sX + rb * BB, xin + rb * BB, xr * BB * 4, mb0 + c * 8);
                    int hrb = max(rb, Din) - Din;        // first h row
                    int hre = re - Din;
                    if (hre > hrb)
                        bulk_g2s(sX + (Din + hrb) * BB, hin + hrb * BB,
                                 (hre - hrb) * BB * 4, mb0 + c * 8);
                }
            }

            // ---- wait only this warp's chunk, then GEMM over its k-range ----
            mbar_wait(mb0 + kg * 8, par);

            const int ke = min(kb + Q, KTOT);
            unsigned long long a0, a1, a2, a3, a4, a5, a6, a7;
            if (kg == 0) {
                a0 = a1 = splat2(sB[r0 + 0]);
                a2 = a3 = splat2(sB[r0 + 1]);
                a4 = a5 = splat2(sB[r0 + 2]);
                a6 = a7 = splat2(sB[r0 + 3]);
            } else {
                a0 = a1 = a2 = a3 = a4 = a5 = a6 = a7 = 0ull;
            }

            #pragma unroll 4
            for (int k = kb; k < ke; ++k) {
                ulonglong2 xv = *(const ulonglong2*)(sX + k * BB + b0i);
                ulonglong2 wA = *(const ulonglong2*)(sW + k * 16 + r0);
                ulonglong2 wB = *(const ulonglong2*)(sW + k * 16 + r0 + 2);
                a0 = fma2(xv.x, wA.x, a0);  a1 = fma2(xv.y, wA.x, a1);
                a2 = fma2(xv.x, wA.y, a2);  a3 = fma2(xv.y, wA.y, a3);
                a4 = fma2(xv.x, wB.x, a4);  a5 = fma2(xv.y, wB.x, a5);
                a6 = fma2(xv.x, wB.y, a6);  a7 = fma2(xv.y, wB.y, a7);
            }

            // write k-split partials
            float* pp = sP + kg * (16 * BB);
            *(ulonglong2*)(pp + (r0 + 0) * BB + b0i) = make_ulonglong2(a0, a1);
            *(ulonglong2*)(pp + (r0 + 1) * BB + b0i) = make_ulonglong2(a2, a3);
            *(ulonglong2*)(pp + (r0 + 2) * BB + b0i) = make_ulonglong2(a4, a5);
            *(ulonglong2*)(pp + (r0 + 3) * BB + b0i) = make_ulonglong2(a6, a7);
            __syncthreads();

            // ---- elementwise + state update: 1 item/thread ----
            {
                float* hout = g_h + (l * 2 + (t & 1)) * HH * BB;
                int b = tid & 63, jj = tid >> 6;
                float iv = 0.f, fv = 0.f, gv = 0.f, ov = 0.f;
                #pragma unroll
                for (int c = 0; c < NCHUNK; ++c) {
                    const float* p = sP + c * (16 * BB);
                    iv += p[(0  + jj) * BB + b];
                    fv += p[(4  + jj) * BB + b];
                    gv += p[(8  + jj) * BB + b];
                    ov += p[(12 + jj) * BB + b];
                }
                float co = sC[jj * BB + b];
                float ig = 1.f / (1.f + expf(-iv));
                float fg = 1.f / (1.f + expf(-fv));
                float og = 1.f / (1.f + expf(-ov));
                float cn = fg * co + ig * tanhf(gv);
                float hn = og * tanhf(cn);
                bool  m  = (t < sLen[b]);
                int   j  = j0 + jj;
                float hpv = sX[(Din + j) * BB + b];   // frozen value if past length
                sC[jj * BB + b]  = m ? cn : co;
                hout[j * BB + b] = m ? hn : hpv;
            }
        }

        // ---- distributed flag barrier (release/acquire, no L1 flush) ----
        __syncthreads();
        if (tid == 0) {
            asm volatile("fence.proxy.async;" ::: "memory");  // STG h -> async-proxy bulk reads
            asm volatile("st.global.release.gpu.u32 [%0], %1;"
                         :: "l"(g_flag + cta * 32), "r"(phase) : "memory");
        }
        if (tid < NCTA) {
            unsigned r;
            do {
                asm volatile("ld.global.acquire.gpu.u32 %0, [%1];"
                             : "=r"(r) : "l"(g_flag + tid * 32));
                if (r >= phase) break;
                __nanosleep(20);
            } while (true);
        }
        __syncthreads();
    }

    // ---- final FC on CTA 0 (L1-bypassing reads of h2) ----
    if (cta == 0) {
        const float* h2 = g_h + (2 * 2 + ((TT - 1) & 1)) * HH * BB;
        for (int it = tid; it < BB * NOUT; it += TB) {
            int b = it / NOUT, o = it - b * NOUT;
            float acc = fcb[o];
            #pragma unroll 4
            for (int j = 0; j < HH; ++j)
                acc += __ldcv(h2 + j * BB + b) * fcw[o * HH + j];
            out[b * NOUT + o] = acc;
        }
    }
}

// ---------------- launch ----------------
extern "C" void kernel_launch(void* const* d_in, const int* in_sizes, int n_in,
                              void* d_out, int out_size) {
    const float* x       = (const float*)d_in[0];
    const int*   lengths = (const int*)  d_in[1];
    const float* Wih0    = (const float*)d_in[2];
    const float* Whh0    = (const float*)d_in[3];
    const float* b0      = (const float*)d_in[4];
    const float* Wih1    = (const float*)d_in[5];
    const float* Whh1    = (const float*)d_in[6];
    const float* b1      = (const float*)d_in[7];
    const float* Wih2    = (const float*)d_in[8];
    const float* Whh2    = (const float*)d_in[9];
    const float* b2      = (const float*)d_in[10];
    const float* fcw     = (const float*)d_in[11];
    const float* fcb     = (const float*)d_in[12];
    float* out = (float*)d_out;

    static bool attr_set = false;
    if (!attr_set) {
        cudaFuncSetAttribute(k_lstm, cudaFuncAttributeMaxDynamicSharedMemorySize, SMEM_BYTES);
        attr_set = true;
    }

    k_init<<<64, 256>>>();
    k_transpose<<<TT, 256>>>(x);
    k_lstm<<<NCTA, TB, SMEM_BYTES>>>(lengths,
                                     Wih0, Whh0, b0,
                                     Wih1, Whh1, b1,
                                     Wih2, Whh2, b2,
                                     fcw, fcb, out);
}